// round 16
// baseline (speedup 1.0000x reference)
#include <cuda_runtime.h>
#include <cuda_fp16.h>
#include <math.h>
#include <stdint.h>

// ---------------------------------------------------------------------------
// SparseMoE on GB300 (sm_103a) — R16
//   Base: R9 (803.6us best). R14/R15 occ-2 GEMM2: neutral. Remaining gap =
//   per-iteration barrier/issue fixed cost at TK=32.
//   R16: TK 32 -> 64 (half the barrier crossings, identical accumulation
//   order -> bitwise-same results), NSTAGE 3 x 54KB stages, xprep fused
//   into router (saves a launch + full x re-read). GEMM configs otherwise
//   R9-exact (TN=256, occ 1, atomic GEMM2 epilogue).
// ---------------------------------------------------------------------------

#define HIDDEN 1024
#define INTER  4096
#define NEXP   8
#define MAXT   4096
#define MAXPAIRS (MAXT*2)

#define TM 128
#define TN 256
#define TK 64                       // k per smem stage (4 x k16 mma chunks)
#define APITCH 144                  // bytes per A smem row (128 data + 16 pad)
#define BPITCH 144                  // bytes per B smem row
#define ABYTES (TM*APITCH)          // 18432
#define BBYTES (TN*BPITCH)          // 36864
#define STAGE_BYTES (ABYTES+BBYTES) // 55296
#define NSTAGE 3                    // 165888 B dynamic smem, occ 1

// ---- device scratch ----
__device__ int2   g_tsel[MAXT];
__device__ float2 g_tw[MAXT];
__device__ int    g_rowtok[MAXPAIRS];
__device__ float  g_roww[MAXPAIRS];
__device__ int    g_count[NEXP];
__device__ int    g_offset[NEXP];
__device__ __half g_xh[(size_t)MAXT * HIDDEN];           // fp16 x, k-permuted
__device__ __half g_w1h[(size_t)NEXP * INTER * HIDDEN];  // w1^T [e][n][k] perm
__device__ __half g_w2h[(size_t)NEXP * HIDDEN * INTER];  // w2^T [e][n][k] perm
__device__ __half g_h1h[(size_t)MAXPAIRS * INTER];       // fp16 gelu rows, perm

// ---------------------------------------------------------------------------
// helpers
// ---------------------------------------------------------------------------
__device__ __forceinline__ float gelu_exact(float x) {
    return 0.5f * x * (1.0f + erff(x * 0.70710678118654752f));
}
__device__ __forceinline__ void cp16(uint32_t dst, const void* src) {
    asm volatile("cp.async.cg.shared.global [%0], [%1], 16;\n" :: "r"(dst), "l"(src));
}
__device__ __forceinline__ void cp_commit() {
    asm volatile("cp.async.commit_group;\n");
}
template <int N> __device__ __forceinline__ void cp_wait() {
    asm volatile("cp.async.wait_group %0;\n" :: "n"(N));
}
__device__ __forceinline__ void mma_fp16(float c[4],
                                         uint32_t a0, uint32_t a1,
                                         uint32_t a2, uint32_t a3,
                                         uint32_t b0, uint32_t b1) {
    asm volatile(
        "mma.sync.aligned.m16n8k16.row.col.f32.f16.f16.f32 "
        "{%0,%1,%2,%3}, {%4,%5,%6,%7}, {%8,%9}, {%0,%1,%2,%3};\n"
        : "+f"(c[0]), "+f"(c[1]), "+f"(c[2]), "+f"(c[3])
        : "r"(a0), "r"(a1), "r"(a2), "r"(a3), "r"(b0), "r"(b1));
}
__device__ __forceinline__ uint32_t pack_h2(float x, float y) {
    __half2 h = __floats2half2_rn(x, y);
    return *(uint32_t*)&h;
}

// ---------------------------------------------------------------------------
// 1) router (fp32 exact) + fused xprep (fp16 k-permuted x) + out zeroing
// ---------------------------------------------------------------------------
__global__ void router_kernel(const float* __restrict__ x,
                              const float* __restrict__ gw,
                              float* __restrict__ out,
                              float* __restrict__ out_logits,
                              int write_logits) {
    int t = blockIdx.x;
    __shared__ float sx[HIDDEN];
    __shared__ float slog[NEXP];

    int tid = threadIdx.x;
    ((float4*)sx)[tid] = ((const float4*)(x + (size_t)t * HIDDEN))[tid];
    __syncthreads();

    int e = tid >> 5;
    int lane = tid & 31;
    float acc = 0.f;
    #pragma unroll 8
    for (int i = lane; i < HIDDEN; i += 32)
        acc += sx[i] * gw[i * NEXP + e];
    #pragma unroll
    for (int o = 16; o > 0; o >>= 1)
        acc += __shfl_down_sync(0xffffffffu, acc, o);
    if (lane == 0) slog[e] = acc;
    __syncthreads();

    if (tid == 0) {
        float l[NEXP];
        float m = -1e30f;
        #pragma unroll
        for (int i = 0; i < NEXP; i++) { l[i] = slog[i]; m = fmaxf(m, l[i]); }
        float p[NEXP];
        #pragma unroll
        for (int i = 0; i < NEXP; i++) p[i] = __expf(l[i] - m);
        int i1 = 0;
        #pragma unroll
        for (int i = 1; i < NEXP; i++) if (p[i] > p[i1]) i1 = i;
        int i2 = (i1 == 0) ? 1 : 0;
        #pragma unroll
        for (int i = 0; i < NEXP; i++)
            if (i != i1 && p[i] > p[i2]) i2 = i;
        float s = p[i1] + p[i2];
        g_tsel[t] = make_int2(i1, i2);
        g_tw[t]   = make_float2(p[i1] / s, p[i2] / s);
    }
    if (write_logits && tid < NEXP)
        out_logits[(size_t)t * NEXP + tid] = slog[tid];

    // fused xprep: 64 16-groups per token; threads 0..63, one group each
    // (u32 slot w (0..7): source pair j0 = (w>>1)*2 + (w&1)*8)
    if (tid < HIDDEN / 16) {
        const float* src = sx + tid * 16;
        uint32_t* dst = (uint32_t*)g_xh + ((size_t)t * (HIDDEN / 16) + tid) * 8;
        #pragma unroll
        for (int w = 0; w < 8; w++) {
            int j0 = ((w >> 1) * 2) + ((w & 1) * 8);
            dst[w] = pack_h2(src[j0], src[j0 + 1]);
        }
    }
    // zero out row t (GEMM2 atomics accumulate across graph replays)
    ((float4*)(out + (size_t)t * HIDDEN))[tid] = make_float4(0.f, 0.f, 0.f, 0.f);
}

// ---------------------------------------------------------------------------
// 2) deterministic compaction (Hillis-Steele scan, no atomics)
// ---------------------------------------------------------------------------
__global__ void scan_kernel(int T) {
    __shared__ int s[1024 * NEXP];
    __shared__ int s_off[NEXP];
    int tid = threadIdx.x;
    int tp = T / 1024;
    int t0 = tid * tp;

    int loc[NEXP];
    #pragma unroll
    for (int e = 0; e < NEXP; e++) loc[e] = 0;

    int2  sel[4];
    float2 wt[4];
    for (int j = 0; j < tp; j++) {
        sel[j] = g_tsel[t0 + j];
        wt[j]  = g_tw[t0 + j];
        loc[sel[j].x]++;
        loc[sel[j].y]++;
    }

    int val[NEXP];
    #pragma unroll
    for (int e = 0; e < NEXP; e++) { val[e] = loc[e]; s[tid * NEXP + e] = val[e]; }

    for (int off = 1; off < 1024; off <<= 1) {
        __syncthreads();
        int add[NEXP];
        #pragma unroll
        for (int e = 0; e < NEXP; e++)
            add[e] = (tid >= off) ? s[(tid - off) * NEXP + e] : 0;
        __syncthreads();
        #pragma unroll
        for (int e = 0; e < NEXP; e++) { val[e] += add[e]; s[tid * NEXP + e] = val[e]; }
    }
    __syncthreads();

    if (tid == 0) {
        int o = 0;
        for (int e = 0; e < NEXP; e++) {
            int tot = s[1023 * NEXP + e];
            g_count[e]  = tot;
            g_offset[e] = o;
            s_off[e]    = o;
            o += tot;
        }
    }
    __syncthreads();

    int pos[NEXP];
    #pragma unroll
    for (int e = 0; e < NEXP; e++) pos[e] = s_off[e] + (val[e] - loc[e]);

    for (int j = 0; j < tp; j++) {
        int t = t0 + j;
        int e0 = sel[j].x, e1 = sel[j].y;
        int i0 = pos[e0]++;
        g_rowtok[i0] = t * 2;     g_roww[i0] = wt[j].x;
        int i1 = pos[e1]++;
        g_rowtok[i1] = t * 2 + 1; g_roww[i1] = wt[j].y;
    }
}

// ---------------------------------------------------------------------------
// 3) wprep (R13, measured 39us): w [e][K][N] f32 -> wt [e][N][K] fp16,
//    k-permuted; 4-lane groups store 64B contiguous.
// ---------------------------------------------------------------------------
template <int WS>
__global__ void wprep_kernel(const float* __restrict__ w, int K, int N) {
    __shared__ float s[32][260];
    __half* wt = (WS == 1) ? (__half*)g_w1h : (__half*)g_w2h;
    const float* We = w + (size_t)blockIdx.z * K * N;
    __half* Wte = wt + (size_t)blockIdx.z * (size_t)K * N;
    int k0 = blockIdx.x * 32, n0 = blockIdx.y * 256;
    int tid = threadIdx.x;

    #pragma unroll
    for (int j = 0; j < 8; j++) {
        int f  = tid + 256 * j;
        int kr = f >> 6;
        int c4 = f & 63;
        float4 v = *(const float4*)(We + (size_t)(k0 + kr) * N + n0 + 4 * c4);
        s[kr][4 * c4 + 0] = v.x;
        s[kr][4 * c4 + 1] = v.y;
        s[kr][4 * c4 + 2] = v.z;
        s[kr][4 * c4 + 3] = v.w;
    }
    __syncthreads();

    const int q  = tid & 3;
    const int r0 = tid >> 2;
    #pragma unroll
    for (int pass = 0; pass < 4; pass++) {
        int n = r0 + 64 * pass;
        uint32_t buf[4];
        #pragma unroll
        for (int u = 0; u < 4; u++) {
            int ww   = q * 4 + u;
            int kk16 = ww >> 3, w8 = ww & 7;
            int j0 = ((w8 >> 1) * 2) + ((w8 & 1) * 8) + kk16 * 16;
            buf[u] = pack_h2(s[j0][n], s[j0 + 1][n]);
        }
        ((uint4*)(Wte + (size_t)(n0 + n) * K + k0))[q] =
            make_uint4(buf[0], buf[1], buf[2], buf[3]);
    }
}

// ---------------------------------------------------------------------------
// 4/5) grouped GEMM — fp16 mma.sync m16n8k16, 128x256x64 tiles,
//      3-stage cp.async, 8 warps (2m x 4n, warp tile 64x64).
//   MODE 1: A = g_xh gathered rows -> g_h1h = fp16(gelu(.)), k-permuted
//   MODE 2: A = g_h1h rows -> atomicAdd(out, wgt * .)
// ---------------------------------------------------------------------------
template <int MODE>
__global__ __launch_bounds__(256, 1)
void moe_gemm(float* __restrict__ out) {
    constexpr int K  = (MODE == 1) ? HIDDEN : INTER;
    constexpr int N  = (MODE == 1) ? INTER  : HIDDEN;
    constexpr int KI = K / TK;               // 16 (GEMM1) / 64 (GEMM2)

    extern __shared__ char smem_raw[];
    const int e = blockIdx.z;
    const int count = g_count[e];
    const int m0 = blockIdx.y * TM;
    if (m0 >= count) return;
    const int off = g_offset[e];
    const int n0 = blockIdx.x * TN;

    const __half* Aglob = (MODE == 1) ? (const __half*)g_xh : (const __half*)g_h1h;
    const __half* Wb = ((MODE == 1) ? (const __half*)g_w1h : (const __half*)g_w2h)
                       + (size_t)e * (size_t)K * N;

    const int tid  = threadIdx.x;
    const int lane = tid & 31;
    const int warp = tid >> 5;
    const int q    = lane & 3;
    const int lr   = lane >> 2;
    const int wrow = (warp & 1) * 64;
    const int wcol = (warp >> 1) * 64;

    const uint32_t sbase = (uint32_t)__cvta_generic_to_shared(smem_raw);

    // A source: one gathered row per thread (row tid>>1, 64B half per thread)
    const __half* arow;
    {
        int r  = tid >> 1;
        int gr = m0 + r;
        int rr = (gr < count) ? gr : (count - 1);
        int src = (MODE == 1) ? (g_rowtok[off + rr] >> 1) : (off + rr);
        arow = Aglob + (size_t)src * K;
    }
    const int ah = (tid & 1) * 64;           // byte offset of this thread's half

    auto issue_stage = [&](int ki) {
        const uint32_t sa = sbase + (ki % NSTAGE) * STAGE_BYTES;
        const uint32_t sb = sa + ABYTES;
        const int kb = ki * 128;             // byte offset of k-window in row
        {
            int r = tid >> 1;
            #pragma unroll
            for (int j = 0; j < 4; j++)
                cp16(sa + (uint32_t)(r * APITCH + ah + j * 16),
                     (const char*)arow + kb + ah + j * 16);
        }
        {
            const char* bsrc = (const char*)(Wb + (size_t)(n0 + tid) * K) + kb;
            const uint32_t bdst = sb + (uint32_t)(tid * BPITCH);
            #pragma unroll
            for (int j = 0; j < 8; j++)
                cp16(bdst + j * 16, bsrc + j * 16);
        }
    };

    float c[4][8][4];
    #pragma unroll
    for (int i = 0; i < 4; i++)
        #pragma unroll
        for (int j = 0; j < 8; j++)
            #pragma unroll
            for (int r = 0; r < 4; r++) c[i][j][r] = 0.f;

    issue_stage(0); cp_commit();
    issue_stage(1); cp_commit();

    for (int i = 0; i < KI; i++) {
        cp_wait<1>();
        __syncthreads();
        if (i + 2 < KI) issue_stage(i + 2);
        cp_commit();

        const char* sp  = smem_raw + (i % NSTAGE) * STAGE_BYTES;
        const char* spB = sp + ABYTES;

        #pragma unroll
        for (int cc = 0; cc < 4; cc++) {      // four k16 chunks
            const int co = cc * 32 + q * 8;   // byte offset within row
            uint32_t a[4][4];
            #pragma unroll
            for (int im = 0; im < 4; im++) {
                int row = wrow + im * 16 + lr;
                uint2 v0 = *(const uint2*)(sp + row * APITCH + co);
                uint2 v1 = *(const uint2*)(sp + (row + 8) * APITCH + co);
                a[im][0] = v0.x;
                a[im][1] = v1.x;
                a[im][2] = v0.y;
                a[im][3] = v1.y;
            }
            uint32_t b[8][2];
            #pragma unroll
            for (int jn = 0; jn < 8; jn++) {
                int nn = wcol + jn * 8 + lr;
                uint2 v = *(const uint2*)(spB + nn * BPITCH + co);
                b[jn][0] = v.x;
                b[jn][1] = v.y;
            }
            #pragma unroll
            for (int im = 0; im < 4; im++)
                #pragma unroll
                for (int jn = 0; jn < 8; jn++)
                    mma_fp16(c[im][jn], a[im][0], a[im][1], a[im][2], a[im][3],
                             b[jn][0], b[jn][1]);
        }
    }

    // epilogue: c0,c1 = (lr, n 2q,2q+1); c2,c3 = (lr+8, same)
    #pragma unroll
    for (int im = 0; im < 4; im++) {
        #pragma unroll
        for (int half = 0; half < 2; half++) {
            int m  = wrow + im * 16 + lr + 8 * half;
            int gr = m0 + m;
            if (gr >= count) continue;
            if (MODE == 1) {
                // write fp16(gelu) in k-permuted layout for GEMM2's A reads
                __half* dst = (__half*)g_h1h + (size_t)(off + gr) * N;
                #pragma unroll
                for (int jn = 0; jn < 8; jn++) {
                    float v0 = gelu_exact(c[im][jn][half * 2]);
                    float v1 = gelu_exact(c[im][jn][half * 2 + 1]);
                    int pos = n0 + wcol + (jn >> 1) * 16 + q * 4 + (jn & 1) * 2;
                    *(uint32_t*)(dst + pos) = pack_h2(v0, v1);
                }
            } else {
                int info  = g_rowtok[off + gr];
                float wgt = g_roww[off + gr];
                float* dst = out + (size_t)(info >> 1) * N;
                #pragma unroll
                for (int jn = 0; jn < 8; jn++) {
                    int n = n0 + wcol + jn * 8 + q * 2;
                    atomicAdd(dst + n,     wgt * c[im][jn][half * 2]);
                    atomicAdd(dst + n + 1, wgt * c[im][jn][half * 2 + 1]);
                }
            }
        }
    }
}

// ---------------------------------------------------------------------------
extern "C" void kernel_launch(void* const* d_in, const int* in_sizes, int n_in,
                              void* d_out, int out_size) {
    const float* x  = (const float*)d_in[0];
    const float* gw = (const float*)d_in[1];
    const float* w1 = (const float*)d_in[2];
    const float* w2 = (const float*)d_in[3];
    float* out = (float*)d_out;

    const int T = in_sizes[0] / HIDDEN;

    int write_logits = (out_size >= T * HIDDEN + T * NEXP) ? 1 : 0;
    float* logits_ptr = out + (size_t)T * HIDDEN;

    const int smem_bytes = NSTAGE * STAGE_BYTES;   // 165888
    cudaFuncSetAttribute(moe_gemm<1>, cudaFuncAttributeMaxDynamicSharedMemorySize, smem_bytes);
    cudaFuncSetAttribute(moe_gemm<2>, cudaFuncAttributeMaxDynamicSharedMemorySize, smem_bytes);

    // 1) router + fused xprep + out zeroing
    router_kernel<<<T, 256>>>(x, gw, out, logits_ptr, write_logits);

    // 2) deterministic compaction
    scan_kernel<<<1, 1024>>>(T);

    // 3) weights -> transposed fp16 (k-permuted)
    {
        dim3 g1(HIDDEN / 32, INTER / 256, NEXP);
        wprep_kernel<1><<<g1, 256>>>(w1, HIDDEN, INTER);
        dim3 g2(INTER / 32, HIDDEN / 256, NEXP);
        wprep_kernel<2><<<g2, 256>>>(w2, INTER, HIDDEN);
    }

    // 4) GEMM1: h1 = fp16(gelu(x_g @ w1[e]))   K=HIDDEN, N=INTER
    {
        dim3 grid(INTER / TN, MAXT / TM, NEXP);
        moe_gemm<1><<<grid, 256, smem_bytes>>>(out);
    }

    // 5) GEMM2: out += wgt * (h1 @ w2[e])      K=INTER, N=HIDDEN
    {
        dim3 grid(HIDDEN / TN, MAXT / TM, NEXP);
        moe_gemm<2><<<grid, 256, smem_bytes>>>(out);
    }
}

// round 17
// speedup vs baseline: 1.1526x; 1.1526x over previous
#include <cuda_runtime.h>
#include <cuda_fp16.h>
#include <math.h>
#include <stdint.h>

// ---------------------------------------------------------------------------
// SparseMoE on GB300 (sm_103a) — R17
//   Strict recombination of measured-best pieces (no new mechanisms):
//     GEMMs  = R9-verbatim (803.6us best): fp16 m16n8k16, 128x256x32,
//              4-stage cp.async, pitch 80, occ 1, atomic GEMM2 epilogue.
//     wprep  = R13 coalesced version (48.8 -> 39.0us measured).
//     xprep  = R14 version with out-zeroing fused (kills zero pass).
//   R16 lesson: TK=64 halved pipeline depth (1 stage ahead) + pitch-144
//   bank conflicts -> 923us. Reverted entirely.
// ---------------------------------------------------------------------------

#define HIDDEN 1024
#define INTER  4096
#define NEXP   8
#define MAXT   4096
#define MAXPAIRS (MAXT*2)

#define TM 128
#define TN 256
#define TK 32                      // k per smem stage (2 x k16 mma chunks)
#define APITCH 80                  // bytes per A smem row (64 data + 16 pad)
#define BPITCH 80                  // bytes per B smem row
#define ABYTES (TM*APITCH)         // 10240
#define BBYTES (TN*BPITCH)         // 20480
#define STAGE_BYTES (ABYTES+BBYTES)// 30720
#define NSTAGE 4                   // 122880 B dynamic smem

// ---- device scratch ----
__device__ int2   g_tsel[MAXT];
__device__ float2 g_tw[MAXT];
__device__ int    g_rowtok[MAXPAIRS];
__device__ float  g_roww[MAXPAIRS];
__device__ int    g_count[NEXP];
__device__ int    g_offset[NEXP];
__device__ __half g_xh[(size_t)MAXT * HIDDEN];           // fp16 x, k-permuted
__device__ __half g_w1h[(size_t)NEXP * INTER * HIDDEN];  // w1^T [e][n][k] perm
__device__ __half g_w2h[(size_t)NEXP * HIDDEN * INTER];  // w2^T [e][n][k] perm
__device__ __half g_h1h[(size_t)MAXPAIRS * INTER];       // fp16 gelu rows, perm

// ---------------------------------------------------------------------------
// helpers
// ---------------------------------------------------------------------------
__device__ __forceinline__ float gelu_exact(float x) {
    return 0.5f * x * (1.0f + erff(x * 0.70710678118654752f));
}
__device__ __forceinline__ void cp16(uint32_t dst, const void* src) {
    asm volatile("cp.async.cg.shared.global [%0], [%1], 16;\n" :: "r"(dst), "l"(src));
}
__device__ __forceinline__ void cp_commit() {
    asm volatile("cp.async.commit_group;\n");
}
template <int N> __device__ __forceinline__ void cp_wait() {
    asm volatile("cp.async.wait_group %0;\n" :: "n"(N));
}
__device__ __forceinline__ void mma_fp16(float c[4],
                                         uint32_t a0, uint32_t a1,
                                         uint32_t a2, uint32_t a3,
                                         uint32_t b0, uint32_t b1) {
    asm volatile(
        "mma.sync.aligned.m16n8k16.row.col.f32.f16.f16.f32 "
        "{%0,%1,%2,%3}, {%4,%5,%6,%7}, {%8,%9}, {%0,%1,%2,%3};\n"
        : "+f"(c[0]), "+f"(c[1]), "+f"(c[2]), "+f"(c[3])
        : "r"(a0), "r"(a1), "r"(a2), "r"(a3), "r"(b0), "r"(b1));
}
__device__ __forceinline__ uint32_t pack_h2(float x, float y) {
    __half2 h = __floats2half2_rn(x, y);
    return *(uint32_t*)&h;
}

// ---------------------------------------------------------------------------
// 1) router (fp32 exact)
// ---------------------------------------------------------------------------
__global__ void router_kernel(const float* __restrict__ x,
                              const float* __restrict__ gw,
                              float* __restrict__ out_logits,
                              int write_logits) {
    int t = blockIdx.x;
    __shared__ float sx[HIDDEN];
    __shared__ float slog[NEXP];

    int tid = threadIdx.x;
    ((float4*)sx)[tid] = ((const float4*)(x + (size_t)t * HIDDEN))[tid];
    __syncthreads();

    int e = tid >> 5;
    int lane = tid & 31;
    float acc = 0.f;
    #pragma unroll 8
    for (int i = lane; i < HIDDEN; i += 32)
        acc += sx[i] * gw[i * NEXP + e];
    #pragma unroll
    for (int o = 16; o > 0; o >>= 1)
        acc += __shfl_down_sync(0xffffffffu, acc, o);
    if (lane == 0) slog[e] = acc;
    __syncthreads();

    if (tid == 0) {
        float l[NEXP];
        float m = -1e30f;
        #pragma unroll
        for (int i = 0; i < NEXP; i++) { l[i] = slog[i]; m = fmaxf(m, l[i]); }
        float p[NEXP];
        #pragma unroll
        for (int i = 0; i < NEXP; i++) p[i] = __expf(l[i] - m);
        int i1 = 0;
        #pragma unroll
        for (int i = 1; i < NEXP; i++) if (p[i] > p[i1]) i1 = i;
        int i2 = (i1 == 0) ? 1 : 0;
        #pragma unroll
        for (int i = 0; i < NEXP; i++)
            if (i != i1 && p[i] > p[i2]) i2 = i;
        float s = p[i1] + p[i2];
        g_tsel[t] = make_int2(i1, i2);
        g_tw[t]   = make_float2(p[i1] / s, p[i2] / s);
    }
    if (write_logits && tid < NEXP)
        out_logits[(size_t)t * NEXP + tid] = slog[tid];
}

// ---------------------------------------------------------------------------
// 2) deterministic compaction (Hillis-Steele scan, no atomics)
// ---------------------------------------------------------------------------
__global__ void scan_kernel(int T) {
    __shared__ int s[1024 * NEXP];
    __shared__ int s_off[NEXP];
    int tid = threadIdx.x;
    int tp = T / 1024;
    int t0 = tid * tp;

    int loc[NEXP];
    #pragma unroll
    for (int e = 0; e < NEXP; e++) loc[e] = 0;

    int2  sel[4];
    float2 wt[4];
    for (int j = 0; j < tp; j++) {
        sel[j] = g_tsel[t0 + j];
        wt[j]  = g_tw[t0 + j];
        loc[sel[j].x]++;
        loc[sel[j].y]++;
    }

    int val[NEXP];
    #pragma unroll
    for (int e = 0; e < NEXP; e++) { val[e] = loc[e]; s[tid * NEXP + e] = val[e]; }

    for (int off = 1; off < 1024; off <<= 1) {
        __syncthreads();
        int add[NEXP];
        #pragma unroll
        for (int e = 0; e < NEXP; e++)
            add[e] = (tid >= off) ? s[(tid - off) * NEXP + e] : 0;
        __syncthreads();
        #pragma unroll
        for (int e = 0; e < NEXP; e++) { val[e] += add[e]; s[tid * NEXP + e] = val[e]; }
    }
    __syncthreads();

    if (tid == 0) {
        int o = 0;
        for (int e = 0; e < NEXP; e++) {
            int tot = s[1023 * NEXP + e];
            g_count[e]  = tot;
            g_offset[e] = o;
            s_off[e]    = o;
            o += tot;
        }
    }
    __syncthreads();

    int pos[NEXP];
    #pragma unroll
    for (int e = 0; e < NEXP; e++) pos[e] = s_off[e] + (val[e] - loc[e]);

    for (int j = 0; j < tp; j++) {
        int t = t0 + j;
        int e0 = sel[j].x, e1 = sel[j].y;
        int i0 = pos[e0]++;
        g_rowtok[i0] = t * 2;     g_roww[i0] = wt[j].x;
        int i1 = pos[e1]++;
        g_rowtok[i1] = t * 2 + 1; g_roww[i1] = wt[j].y;
    }
}

// ---------------------------------------------------------------------------
// 3) xprep: x -> fp16 k-permuted; also zeroes matching out region
//    (u32 slot w (0..7): source pair j0 = (w>>1)*2 + (w&1)*8)
// ---------------------------------------------------------------------------
__global__ void xprep_kernel(const float* __restrict__ x,
                             float* __restrict__ out) {
    size_t gi = (size_t)blockIdx.x * blockDim.x + threadIdx.x;  // 16-group idx
    const float* src = x + gi * 16;
    uint32_t* dst = (uint32_t*)g_xh + gi * 8;
    float v[16];
    #pragma unroll
    for (int j = 0; j < 16; j += 4) {
        float4 f = *(const float4*)(src + j);
        v[j] = f.x; v[j + 1] = f.y; v[j + 2] = f.z; v[j + 3] = f.w;
    }
    #pragma unroll
    for (int w = 0; w < 8; w++) {
        int j0 = ((w >> 1) * 2) + ((w & 1) * 8);
        dst[w] = pack_h2(v[j0], v[j0 + 1]);
    }
    // zero 16 floats of out (GEMM2 atomics accumulate across graph replays)
    float4 z = make_float4(0.f, 0.f, 0.f, 0.f);
    float4* o = (float4*)(out + gi * 16);
    o[0] = z; o[1] = z; o[2] = z; o[3] = z;
}

// ---------------------------------------------------------------------------
// 4) wprep (R13, measured 39us): w [e][K][N] f32 -> wt [e][N][K] fp16,
//    k-permuted; 4-lane groups store 64B contiguous.
// ---------------------------------------------------------------------------
template <int WS>
__global__ void wprep_kernel(const float* __restrict__ w, int K, int N) {
    __shared__ float s[32][260];
    __half* wt = (WS == 1) ? (__half*)g_w1h : (__half*)g_w2h;
    const float* We = w + (size_t)blockIdx.z * K * N;
    __half* Wte = wt + (size_t)blockIdx.z * (size_t)K * N;
    int k0 = blockIdx.x * 32, n0 = blockIdx.y * 256;
    int tid = threadIdx.x;

    #pragma unroll
    for (int j = 0; j < 8; j++) {
        int f  = tid + 256 * j;
        int kr = f >> 6;
        int c4 = f & 63;
        float4 v = *(const float4*)(We + (size_t)(k0 + kr) * N + n0 + 4 * c4);
        s[kr][4 * c4 + 0] = v.x;
        s[kr][4 * c4 + 1] = v.y;
        s[kr][4 * c4 + 2] = v.z;
        s[kr][4 * c4 + 3] = v.w;
    }
    __syncthreads();

    const int q  = tid & 3;
    const int r0 = tid >> 2;
    #pragma unroll
    for (int pass = 0; pass < 4; pass++) {
        int n = r0 + 64 * pass;
        uint32_t buf[4];
        #pragma unroll
        for (int u = 0; u < 4; u++) {
            int ww   = q * 4 + u;
            int kk16 = ww >> 3, w8 = ww & 7;
            int j0 = ((w8 >> 1) * 2) + ((w8 & 1) * 8) + kk16 * 16;
            buf[u] = pack_h2(s[j0][n], s[j0 + 1][n]);
        }
        ((uint4*)(Wte + (size_t)(n0 + n) * K + k0))[q] =
            make_uint4(buf[0], buf[1], buf[2], buf[3]);
    }
}

// ---------------------------------------------------------------------------
// 5/6) grouped GEMM — R9-verbatim: fp16 mma.sync m16n8k16, 128x256x32,
//      4-stage cp.async, 8 warps (2m x 4n, warp tile 64x64), occ 1.
//   MODE 1: A = g_xh gathered rows -> g_h1h = fp16(gelu(.)), k-permuted
//   MODE 2: A = g_h1h rows -> atomicAdd(out, wgt * .)
// ---------------------------------------------------------------------------
template <int MODE>
__global__ __launch_bounds__(256, 1)
void moe_gemm(float* __restrict__ out) {
    constexpr int K  = (MODE == 1) ? HIDDEN : INTER;
    constexpr int N  = (MODE == 1) ? INTER  : HIDDEN;
    constexpr int KI = K / TK;

    extern __shared__ char smem_raw[];
    const int e = blockIdx.z;
    const int count = g_count[e];
    const int m0 = blockIdx.y * TM;
    if (m0 >= count) return;
    const int off = g_offset[e];
    const int n0 = blockIdx.x * TN;

    const __half* Aglob = (MODE == 1) ? (const __half*)g_xh : (const __half*)g_h1h;
    const __half* Wb = ((MODE == 1) ? (const __half*)g_w1h : (const __half*)g_w2h)
                       + (size_t)e * (size_t)K * N;

    const int tid  = threadIdx.x;
    const int lane = tid & 31;
    const int warp = tid >> 5;
    const int q    = lane & 3;
    const int lr   = lane >> 2;
    const int wrow = (warp & 1) * 64;
    const int wcol = (warp >> 1) * 64;

    const uint32_t sbase = (uint32_t)__cvta_generic_to_shared(smem_raw);

    // A source: one gathered row per thread (row tid>>1, two 16B chunks)
    const __half* arow;
    {
        int r  = tid >> 1;
        int gr = m0 + r;
        int rr = (gr < count) ? gr : (count - 1);
        int src = (MODE == 1) ? (g_rowtok[off + rr] >> 1) : (off + rr);
        arow = Aglob + (size_t)src * K;
    }
    const int ac = (tid & 1) * 2;          // first of two 16B chunks in row

    auto issue_stage = [&](int ki) {
        const uint32_t sa = sbase + (ki % NSTAGE) * STAGE_BYTES;
        const uint32_t sb = sa + ABYTES;
        const int kb = ki * 64;            // byte offset of k-window in row
        {
            int r = tid >> 1;
            cp16(sa + (uint32_t)(r * APITCH + ac * 16),
                 (const char*)arow + kb + ac * 16);
            cp16(sa + (uint32_t)(r * APITCH + (ac + 1) * 16),
                 (const char*)arow + kb + (ac + 1) * 16);
        }
        {
            int c = tid & 3;
            #pragma unroll
            for (int j = 0; j < 4; j++) {
                int n = (tid >> 2) + 64 * j;
                cp16(sb + (uint32_t)(n * BPITCH + c * 16),
                     (const char*)(Wb + (size_t)(n0 + n) * K) + kb + c * 16);
            }
        }
    };

    float c[4][8][4];
    #pragma unroll
    for (int i = 0; i < 4; i++)
        #pragma unroll
        for (int j = 0; j < 8; j++)
            #pragma unroll
            for (int r = 0; r < 4; r++) c[i][j][r] = 0.f;

    issue_stage(0); cp_commit();
    issue_stage(1); cp_commit();
    issue_stage(2); cp_commit();

    for (int i = 0; i < KI; i++) {
        cp_wait<2>();
        __syncthreads();
        if (i + 3 < KI) issue_stage(i + 3);
        cp_commit();

        const char* sp  = smem_raw + (i % NSTAGE) * STAGE_BYTES;
        const char* spB = sp + ABYTES;

        #pragma unroll
        for (int cc = 0; cc < 2; cc++) {          // two k16 chunks
            const int co = cc * 32 + q * 8;       // byte offset within row
            uint32_t a[4][4];
            #pragma unroll
            for (int im = 0; im < 4; im++) {
                int row = wrow + im * 16 + lr;
                uint2 v0 = *(const uint2*)(sp + row * APITCH + co);
                uint2 v1 = *(const uint2*)(sp + (row + 8) * APITCH + co);
                a[im][0] = v0.x;
                a[im][1] = v1.x;
                a[im][2] = v0.y;
                a[im][3] = v1.y;
            }
            uint32_t b[8][2];
            #pragma unroll
            for (int jn = 0; jn < 8; jn++) {
                int nn = wcol + jn * 8 + lr;
                uint2 v = *(const uint2*)(spB + nn * BPITCH + co);
                b[jn][0] = v.x;
                b[jn][1] = v.y;
            }
            #pragma unroll
            for (int im = 0; im < 4; im++)
                #pragma unroll
                for (int jn = 0; jn < 8; jn++)
                    mma_fp16(c[im][jn], a[im][0], a[im][1], a[im][2], a[im][3],
                             b[jn][0], b[jn][1]);
        }
    }

    // epilogue: c0,c1 = (lr, n 2q,2q+1); c2,c3 = (lr+8, same)
    #pragma unroll
    for (int im = 0; im < 4; im++) {
        #pragma unroll
        for (int half = 0; half < 2; half++) {
            int m  = wrow + im * 16 + lr + 8 * half;
            int gr = m0 + m;
            if (gr >= count) continue;
            if (MODE == 1) {
                // write fp16(gelu) in k-permuted layout for GEMM2's A reads
                __half* dst = (__half*)g_h1h + (size_t)(off + gr) * N;
                #pragma unroll
                for (int jn = 0; jn < 8; jn++) {
                    float v0 = gelu_exact(c[im][jn][half * 2]);
                    float v1 = gelu_exact(c[im][jn][half * 2 + 1]);
                    int pos = n0 + wcol + (jn >> 1) * 16 + q * 4 + (jn & 1) * 2;
                    *(uint32_t*)(dst + pos) = pack_h2(v0, v1);
                }
            } else {
                int info  = g_rowtok[off + gr];
                float wgt = g_roww[off + gr];
                float* dst = out + (size_t)(info >> 1) * N;
                #pragma unroll
                for (int jn = 0; jn < 8; jn++) {
                    int n = n0 + wcol + jn * 8 + q * 2;
                    atomicAdd(dst + n,     wgt * c[im][jn][half * 2]);
                    atomicAdd(dst + n + 1, wgt * c[im][jn][half * 2 + 1]);
                }
            }
        }
    }
}

// ---------------------------------------------------------------------------
extern "C" void kernel_launch(void* const* d_in, const int* in_sizes, int n_in,
                              void* d_out, int out_size) {
    const float* x  = (const float*)d_in[0];
    const float* gw = (const float*)d_in[1];
    const float* w1 = (const float*)d_in[2];
    const float* w2 = (const float*)d_in[3];
    float* out = (float*)d_out;

    const int T = in_sizes[0] / HIDDEN;

    int write_logits = (out_size >= T * HIDDEN + T * NEXP) ? 1 : 0;
    float* logits_ptr = out + (size_t)T * HIDDEN;

    const int smem_bytes = NSTAGE * STAGE_BYTES;
    cudaFuncSetAttribute(moe_gemm<1>, cudaFuncAttributeMaxDynamicSharedMemorySize, smem_bytes);
    cudaFuncSetAttribute(moe_gemm<2>, cudaFuncAttributeMaxDynamicSharedMemorySize, smem_bytes);

    // 1) router + 2) compaction
    router_kernel<<<T, 256>>>(x, gw, logits_ptr, write_logits);
    scan_kernel<<<1, 1024>>>(T);

    // 3) x -> fp16 (k-permuted) + zero out region
    xprep_kernel<<<T * (HIDDEN / 16) / 256, 256>>>(x, out);

    // 4) weights -> transposed fp16 (k-permuted)
    {
        dim3 g1(HIDDEN / 32, INTER / 256, NEXP);
        wprep_kernel<1><<<g1, 256>>>(w1, HIDDEN, INTER);
        dim3 g2(INTER / 32, HIDDEN / 256, NEXP);
        wprep_kernel<2><<<g2, 256>>>(w2, INTER, HIDDEN);
    }

    // 5) GEMM1: h1 = fp16(gelu(x_g @ w1[e]))   K=HIDDEN, N=INTER
    {
        dim3 grid(INTER / TN, MAXT / TM, NEXP);
        moe_gemm<1><<<grid, 256, smem_bytes>>>(out);
    }

    // 6) GEMM2: out += wgt * (h1 @ w2[e])      K=INTER, N=HIDDEN
    {
        dim3 grid(HIDDEN / TN, MAXT / TM, NEXP);
        moe_gemm<2><<<grid, 256, smem_bytes>>>(out);
    }
}